// round 8
// baseline (speedup 1.0000x reference)
#include <cuda_runtime.h>
#include <stdint.h>

// Problem constants
#define BB 16
#define CC 4
#define HH 512
#define WW 1024
#define ROWS (BB * CC * HH)       // 32768
#define NBLK (ROWS / 8)           // 4096 blocks, 8 rows each
#define BCN  (BB * CC)            // 64 (b,c) groups; 64 blocks per group

// Per-(b,c) accumulators, padded to 128B stride to spread across L2 slices.
// [bc][0] = err sum, [bc][1] = cnt sum. Zero-initialized at module load; the
// last block resets them after reading, so every graph replay sees zeros.
__device__ float        g_acc[BCN][32];
__device__ unsigned int g_count = 0;

// ---------------------------------------------------------------------------
// Single fused kernel: one warp per row, 8 rows per block.
//  Phase A (all blocks): argmax over W (first-max), gather offsets, mask,
//    block-reduce 8 rows. Warps 1..7 exit after one __syncthreads. Warp 0
//    fires two RED.ADDs and ONE acq_rel counter atomic (lane 0 only) — no
//    second block barrier, so the streaming pipeline never stalls.
//  Phase B (last block's warp 0 only): 32 lanes acquire the counter, read the
//    64 L2-hot accumulator pairs, compute per-group means, write the scalar,
//    reset state for the next graph replay.
// ---------------------------------------------------------------------------
__global__ __launch_bounds__(256) void offset_loss_kernel(
    const float* __restrict__ offset_pred,
    const float* __restrict__ offset_true,
    const float* __restrict__ cls_true,
    const float* __restrict__ vertical_true,
    float* __restrict__ out)
{
    const int warp_in_block = threadIdx.x >> 5;
    const int lane = threadIdx.x & 31;
    const int row = blockIdx.x * 8 + warp_in_block;

    const float4* crow = reinterpret_cast<const float4*>(cls_true + (size_t)row * WW);

    // Front-batch all 8 coalesced float4 loads (512B/warp each) -> MLP 8.
    float4 v[8];
#pragma unroll
    for (int k = 0; k < 8; k++) {
        v[k] = __ldcs(&crow[k * 32 + lane]);   // streaming: read-once data
    }

    // Per-lane scan in increasing index order (first-max within lane).
    float best = -__int_as_float(0x7f800000);  // -inf
    int   bidx = 0;
#pragma unroll
    for (int k = 0; k < 8; k++) {
        const int base = (k * 32 + lane) * 4;
        if (v[k].x > best) { best = v[k].x; bidx = base + 0; }
        if (v[k].y > best) { best = v[k].y; bidx = base + 1; }
        if (v[k].z > best) { best = v[k].z; bidx = base + 2; }
        if (v[k].w > best) { best = v[k].w; bidx = base + 3; }
    }

    // Warp reduction: larger value wins; exact tie -> smaller index (first-max).
#pragma unroll
    for (int off = 16; off > 0; off >>= 1) {
        float oval = __shfl_xor_sync(0xffffffffu, best, off);
        int   oidx = __shfl_xor_sync(0xffffffffu, bidx, off);
        if (oval > best || (oval == best && oidx < bidx)) {
            best = oval;
            bidx = oidx;
        }
    }

    // Lane 0 of each warp: gather + mask for this row.
    __shared__ float s_err[8];
    __shared__ float s_cnt[8];
    if (lane == 0) {
        const size_t gidx = (size_t)row * WW + bidx;
        float p = __ldg(&offset_pred[gidx]);
        float t = __ldg(&offset_true[gidx]);
        float mask = (__ldg(&vertical_true[row]) >= 0.5f) ? 1.0f : 0.0f;
        s_err[warp_in_block] = fabsf(p - t) * mask;
        s_cnt[warp_in_block] = mask;
    }
    __syncthreads();

    // Warps 1..7: done. They retire immediately; no tail stall.
    if (warp_in_block != 0) return;

    // Warp 0: reduce the 8 row results (lanes 0..7 carry data, others 0).
    float e = (lane < 8) ? s_err[lane] : 0.0f;
    float c = (lane < 8) ? s_cnt[lane] : 0.0f;
#pragma unroll
    for (int off = 4; off > 0; off >>= 1) {
        e += __shfl_xor_sync(0xffffffffu, e, off);
        c += __shfl_xor_sync(0xffffffffu, c, off);
    }

    int is_last = 0;
    if (lane == 0) {
        const int bc = blockIdx.x >> 6;         // 64 blocks per group
        atomicAdd(&g_acc[bc][0], e);            // REDG.ADD (no return)
        atomicAdd(&g_acc[bc][1], c);
        unsigned prev;
        asm volatile("atom.acq_rel.gpu.global.add.u32 %0, [%1], 1;"
                     : "=r"(prev) : "l"(&g_count) : "memory");
        is_last = (prev == (unsigned)(NBLK - 1));
    }
    is_last = __shfl_sync(0xffffffffu, is_last, 0);
    if (!is_last) return;

    // ---- Phase B: last block's warp 0 only. Each lane formally acquires the
    // final counter value, pairing with every block's release RMW. ----
    unsigned cnt_obs;
    asm volatile("ld.acquire.gpu.global.u32 %0, [%1];"
                 : "=r"(cnt_obs) : "l"(&g_count) : "memory");
    (void)cnt_obs;

    float pbc = 0.0f;
#pragma unroll
    for (int g = 0; g < 2; g++) {
        const int bc = g * 32 + lane;
        float ge = __ldcg(&g_acc[bc][0]);
        float gc = __ldcg(&g_acc[bc][1]);
        pbc += (gc > 0.0f) ? (ge / fmaxf(gc, 1.0f)) : 0.0f;
        // Reset for next graph replay (visible at kernel boundary).
        g_acc[bc][0] = 0.0f;
        g_acc[bc][1] = 0.0f;
    }
    if (lane == 0) g_count = 0;

#pragma unroll
    for (int off = 16; off > 0; off >>= 1) {
        pbc += __shfl_xor_sync(0xffffffffu, pbc, off);
    }
    if (lane == 0) {
        out[0] = pbc / (float)BB;
    }
}

// ---------------------------------------------------------------------------
extern "C" void kernel_launch(void* const* d_in, const int* in_sizes, int n_in,
                              void* d_out, int out_size)
{
    const float* offset_pred   = (const float*)d_in[0];
    const float* offset_true   = (const float*)d_in[1];
    const float* cls_true      = (const float*)d_in[2];
    const float* vertical_true = (const float*)d_in[3];
    float* out = (float*)d_out;

    offset_loss_kernel<<<NBLK, 256>>>(offset_pred, offset_true, cls_true,
                                      vertical_true, out);
}